// round 14
// baseline (speedup 1.0000x reference)
#include <cuda_runtime.h>
#include <cuda_bf16.h>
#include <math.h>
#include <stdint.h>

// Problem constants
#define Bq   4
#define TTq  4096
#define Cq   1024
#define Hq   16
#define Kq   64
#define TC   64                   // attention chunk length
#define NC   (TTq / TC)           // 64 chunks
#define BT   (Bq * TTq)           // 16384 rows

// ---------------- scratch (static device arrays; no allocation) -------------
// activation hi/lo splits, 4 slices: r,k,v,g
__device__ __nv_bfloat16 g_xh[4 * BT * Cq], g_xl[4 * BT * Cq];
__device__ __nv_bfloat16 g_yh[BT * Cq], g_yl[BT * Cq];
__device__ __nv_bfloat16 g_Wh[5 * Cq * Cq], g_Wl[5 * Cq * Cq];
__device__ float g_o4[4 * BT * Cq];          // r,k,v,g GEMM outputs
__device__ float g_xo[BT * Cq];
__device__ float g_A [NC * Bq * Hq * Kq * Kq];
__device__ float g_S [NC * Bq * Hq * Kq * Kq];

// ---------------- PTX helpers (baseline ISA only) ----------------------------
__device__ __forceinline__ uint32_t smem_u32(const void* p) {
    uint32_t a;
    asm("{ .reg .u64 t; cvta.to.shared.u64 t, %1; cvt.u32.u64 %0, t; }"
        : "=r"(a) : "l"(p));
    return a;
}
__device__ __forceinline__ void cp_async16(uint32_t saddr, const void* gaddr) {
    asm volatile("cp.async.cg.shared.global [%0], [%1], 16;"
                 :: "r"(saddr), "l"(gaddr) : "memory");
}
__device__ __forceinline__ void cp_commit() {
    asm volatile("cp.async.commit_group;" ::: "memory");
}
__device__ __forceinline__ void ldm_x4(uint32_t* r, uint32_t addr) {
    asm volatile("ldmatrix.sync.aligned.m8n8.x4.shared.b16 {%0,%1,%2,%3}, [%4];"
                 : "=r"(r[0]), "=r"(r[1]), "=r"(r[2]), "=r"(r[3]) : "r"(addr));
}
__device__ __forceinline__ void mma_bf16(float* c, const uint32_t* a,
                                         uint32_t b0, uint32_t b1) {
    asm volatile(
        "mma.sync.aligned.m16n8k16.row.col.f32.bf16.bf16.f32 "
        "{%0,%1,%2,%3}, {%4,%5,%6,%7}, {%8,%9}, {%0,%1,%2,%3};"
        : "+f"(c[0]), "+f"(c[1]), "+f"(c[2]), "+f"(c[3])
        : "r"(a[0]), "r"(a[1]), "r"(a[2]), "r"(a[3]), "r"(b0), "r"(b1));
}

// ---------------- 1) time-shift mixing + bf16 hi/lo split -------------------
__device__ __forceinline__ void split_store(float4 o, __nv_bfloat16* hp, __nv_bfloat16* lp) {
    __nv_bfloat16 h0 = __float2bfloat16(o.x), h1 = __float2bfloat16(o.y);
    __nv_bfloat16 h2 = __float2bfloat16(o.z), h3 = __float2bfloat16(o.w);
    __nv_bfloat16 l0 = __float2bfloat16(o.x - __bfloat162float(h0));
    __nv_bfloat16 l1 = __float2bfloat16(o.y - __bfloat162float(h1));
    __nv_bfloat16 l2 = __float2bfloat16(o.z - __bfloat162float(h2));
    __nv_bfloat16 l3 = __float2bfloat16(o.w - __bfloat162float(h3));
    __nv_bfloat162 a; a.x = h0; a.y = h1;
    __nv_bfloat162 b; b.x = h2; b.y = h3;
    *(__nv_bfloat162*)(hp)     = a;
    *(__nv_bfloat162*)(hp + 2) = b;
    a.x = l0; a.y = l1; b.x = l2; b.y = l3;
    *(__nv_bfloat162*)(lp)     = a;
    *(__nv_bfloat162*)(lp + 2) = b;
}

__global__ __launch_bounds__(256)
void mix_split_kernel(const float* __restrict__ x,
                      const float* __restrict__ tmr, const float* __restrict__ tmk,
                      const float* __restrict__ tmv, const float* __restrict__ tmg)
{
    int idx = blockIdx.x * 256 + threadIdx.x;
    int e = idx * 4;
    int c = e & (Cq - 1);
    int bt = e >> 10;
    int tt = bt & (TTq - 1);

    float4 xc = *(const float4*)(x + e);
    float4 xp = make_float4(0.f, 0.f, 0.f, 0.f);
    if (tt != 0) xp = *(const float4*)(x + e - Cq);

    float4 m, o;
    m = *(const float4*)(tmr + c);
    o.x = xc.x * m.x + xp.x * (1.f - m.x); o.y = xc.y * m.y + xp.y * (1.f - m.y);
    o.z = xc.z * m.z + xp.z * (1.f - m.z); o.w = xc.w * m.w + xp.w * (1.f - m.w);
    split_store(o, g_xh + (size_t)0 * BT * Cq + e, g_xl + (size_t)0 * BT * Cq + e);
    m = *(const float4*)(tmk + c);
    o.x = xc.x * m.x + xp.x * (1.f - m.x); o.y = xc.y * m.y + xp.y * (1.f - m.y);
    o.z = xc.z * m.z + xp.z * (1.f - m.z); o.w = xc.w * m.w + xp.w * (1.f - m.w);
    split_store(o, g_xh + (size_t)1 * BT * Cq + e, g_xl + (size_t)1 * BT * Cq + e);
    m = *(const float4*)(tmv + c);
    o.x = xc.x * m.x + xp.x * (1.f - m.x); o.y = xc.y * m.y + xp.y * (1.f - m.y);
    o.z = xc.z * m.z + xp.z * (1.f - m.z); o.w = xc.w * m.w + xp.w * (1.f - m.w);
    split_store(o, g_xh + (size_t)2 * BT * Cq + e, g_xl + (size_t)2 * BT * Cq + e);
    m = *(const float4*)(tmg + c);
    o.x = xc.x * m.x + xp.x * (1.f - m.x); o.y = xc.y * m.y + xp.y * (1.f - m.y);
    o.z = xc.z * m.z + xp.z * (1.f - m.z); o.w = xc.w * m.w + xp.w * (1.f - m.w);
    split_store(o, g_xh + (size_t)3 * BT * Cq + e, g_xl + (size_t)3 * BT * Cq + e);
}

__global__ __launch_bounds__(256)
void wsplit5_kernel(const float* __restrict__ W0, const float* __restrict__ W1,
                    const float* __restrict__ W2, const float* __restrict__ W3,
                    const float* __restrict__ W4,
                    __nv_bfloat16* __restrict__ Wh, __nv_bfloat16* __restrict__ Wl)
{
    int m = blockIdx.y;
    const float* W = (m == 0) ? W0 : (m == 1) ? W1 : (m == 2) ? W2 : (m == 3) ? W3 : W4;
    int e = (blockIdx.x * 256 + threadIdx.x) * 4;
    float4 w = *(const float4*)(W + e);
    split_store(w, Wh + (size_t)m * Cq * Cq + e, Wl + (size_t)m * Cq * Cq + e);
}

// ---------------- 2) bf16x3 HMMA GEMM, persistent + 3-stage, fused combos ---
// C = Ah*Wh^T + Ah*Wl^T + Al*Wh^T per job; job's g selects A/W/C slices.
#define KB      32
#define TILE_B  10240                    // 128 rows * 80B pitch
#define STG4    (4 * TILE_B)             // 40960: Ah|Al|Wh|Wl
#define GSMEM   (3 * STG4)               // 122880, 3 stages
#define NKB     32                       // 1024 / KB
#define GGRID   148

__global__ __launch_bounds__(256, 1)
void gemm_hmma(const __nv_bfloat16* __restrict__ AhB,
               const __nv_bfloat16* __restrict__ AlB,
               const __nv_bfloat16* __restrict__ WhB,
               const __nv_bfloat16* __restrict__ WlB,
               float* __restrict__ CB, int njobs)
{
    extern __shared__ __align__(16) char smem[];
    uint32_t sb = smem_u32(smem);

    int t = threadIdx.x;
    int w = t >> 5, lane = t & 31;
    int wm = w >> 2;            // 0..1  (64-row slab)
    int wn = w & 3;             // 0..3  (32-col slab)

    // per-thread cp.async geometry (offsets within one tile)
    uint32_t so[2]; int rrow[2], rc8[2];
#pragma unroll
    for (int i = 0; i < 2; i++) {
        int lin = t + i * 256;
        rrow[i] = lin >> 2; rc8[i] = (lin & 3) * 8;
        so[i] = (uint32_t)(rrow[i] * 80 + (lin & 3) * 16);
    }
    // ldmatrix per-lane base offsets
    int lr = lane & 7, sel = lane >> 3;
    uint32_t a_lb = (uint32_t)((wm * 64 + lr + (sel & 1) * 8) * 80 + ((sel >> 1) & 1) * 16);
    uint32_t b_lb = (uint32_t)((wn * 32 + lr + (sel >> 1) * 8) * 80 + (sel & 1) * 16);

    for (int job = blockIdx.x; job < njobs; job += GGRID) {
        int g    = job >> 10;
        int tile = job & 1023;
        int bm = tile >> 3, bn = tile & 7;
        const __nv_bfloat16* Ah = AhB + (size_t)g * BT * Cq;
        const __nv_bfloat16* Al = AlB + (size_t)g * BT * Cq;
        const __nv_bfloat16* Wh = WhB + (size_t)g * Cq * Cq;
        const __nv_bfloat16* Wl = WlB + (size_t)g * Cq * Cq;
        float* Cmat = CB + (size_t)g * BT * Cq;

        size_t a_go[2], b_go[2];
#pragma unroll
        for (int i = 0; i < 2; i++) {
            a_go[i] = (size_t)(bm * 128 + rrow[i]) * Cq + rc8[i];
            b_go[i] = (size_t)(bn * 128 + rrow[i]) * Cq + rc8[i];
        }

        float C[4][4][4];
#pragma unroll
        for (int i = 0; i < 4; i++)
#pragma unroll
            for (int j = 0; j < 4; j++)
#pragma unroll
                for (int q = 0; q < 4; q++) C[i][j][q] = 0.f;

        // prologue: stages 0,1 <- kb 0,1
#pragma unroll
        for (int pk = 0; pk < 2; pk++) {
            uint32_t st = sb + pk * STG4;
            int k0 = pk * KB;
#pragma unroll
            for (int i = 0; i < 2; i++) {
                cp_async16(st + so[i],              Ah + a_go[i] + k0);
                cp_async16(st + TILE_B + so[i],     Al + a_go[i] + k0);
                cp_async16(st + 2 * TILE_B + so[i], Wh + b_go[i] + k0);
                cp_async16(st + 3 * TILE_B + so[i], Wl + b_go[i] + k0);
            }
            cp_commit();
        }

        for (int kb = 0; kb < NKB; kb++) {
            if (kb < NKB - 1)
                asm volatile("cp.async.wait_group 1;" ::: "memory");
            else
                asm volatile("cp.async.wait_group 0;" ::: "memory");
            __syncthreads();
            // prefetch kb+2 into stage (kb+2)%3 == (kb-1)%3 (read finished at
            // kb-1; the sync above bounds all warps past that compute)
            if (kb + 2 < NKB) {
                int k0 = (kb + 2) * KB;
                uint32_t st = sb + ((kb + 2) % 3) * STG4;
#pragma unroll
                for (int i = 0; i < 2; i++) {
                    cp_async16(st + so[i],              Ah + a_go[i] + k0);
                    cp_async16(st + TILE_B + so[i],     Al + a_go[i] + k0);
                    cp_async16(st + 2 * TILE_B + so[i], Wh + b_go[i] + k0);
                    cp_async16(st + 3 * TILE_B + so[i], Wl + b_go[i] + k0);
                }
                cp_commit();
            }

            uint32_t base = sb + (kb % 3) * STG4;
#pragma unroll
            for (int s = 0; s < 2; s++) {
                uint32_t aH[4][4], bH[2][4], bL[2][4];
                // combo 1: Ah * Wh
#pragma unroll
                for (int mt = 0; mt < 4; mt++)
                    ldm_x4(aH[mt], base + a_lb + (uint32_t)(mt * 16 * 80 + s * 32));
#pragma unroll
                for (int gg = 0; gg < 2; gg++)
                    ldm_x4(bH[gg], base + 2 * TILE_B + b_lb + (uint32_t)(gg * 16 * 80 + s * 32));
#pragma unroll
                for (int mt = 0; mt < 4; mt++)
#pragma unroll
                    for (int gg = 0; gg < 2; gg++) {
                        mma_bf16(C[mt][2 * gg],     aH[mt], bH[gg][0], bH[gg][1]);
                        mma_bf16(C[mt][2 * gg + 1], aH[mt], bH[gg][2], bH[gg][3]);
                    }
                // combo 2: Ah * Wl  (reuse aH)
#pragma unroll
                for (int gg = 0; gg < 2; gg++)
                    ldm_x4(bL[gg], base + 3 * TILE_B + b_lb + (uint32_t)(gg * 16 * 80 + s * 32));
#pragma unroll
                for (int mt = 0; mt < 4; mt++)
#pragma unroll
                    for (int gg = 0; gg < 2; gg++) {
                        mma_bf16(C[mt][2 * gg],     aH[mt], bL[gg][0], bL[gg][1]);
                        mma_bf16(C[mt][2 * gg + 1], aH[mt], bL[gg][2], bL[gg][3]);
                    }
                // combo 3: Al * Wh  (reuse bH)
                uint32_t aL[4][4];
#pragma unroll
                for (int mt = 0; mt < 4; mt++)
                    ldm_x4(aL[mt], base + TILE_B + a_lb + (uint32_t)(mt * 16 * 80 + s * 32));
#pragma unroll
                for (int mt = 0; mt < 4; mt++)
#pragma unroll
                    for (int gg = 0; gg < 2; gg++) {
                        mma_bf16(C[mt][2 * gg],     aL[mt], bH[gg][0], bH[gg][1]);
                        mma_bf16(C[mt][2 * gg + 1], aL[mt], bH[gg][2], bH[gg][3]);
                    }
            }
        }

        // epilogue
        int row0 = bm * 128 + wm * 64 + (lane >> 2);
        int col0 = bn * 128 + wn * 32 + (lane & 3) * 2;
#pragma unroll
        for (int mt = 0; mt < 4; mt++) {
#pragma unroll
            for (int nt = 0; nt < 4; nt++) {
                float* p0 = Cmat + (size_t)(row0 + mt * 16) * Cq + col0 + nt * 8;
                float* p1 = p0 + 8 * Cq;
                *(float2*)p0 = make_float2(C[mt][nt][0], C[mt][nt][1]);
                *(float2*)p1 = make_float2(C[mt][nt][2], C[mt][nt][3]);
            }
        }
        __syncthreads();   // protect stages 0,1 reuse by next job's prologue
    }
}

// ---------------- 3) Phase A: A_c = k^T diag(wk) v per chunk-head (T=64) ----
__global__ __launch_bounds__(256)
void phaseA_kernel(const float* __restrict__ kbuf, const float* __restrict__ vbuf,
                   const float* __restrict__ td)
{
    __shared__ float ks[TC * Kq], vs[TC * Kq], pw[TC];

    int cb = blockIdx.x;           // ((c*B + b)*H + h)
    int h  = cb & (Hq - 1);
    int b  = (cb >> 4) & (Bq - 1);
    int c  = cb >> 6;
    int t  = threadIdx.x;

    const float* kp = kbuf + ((size_t)(b * TTq + c * TC)) * Cq + h * Kq;
    const float* vp = vbuf + ((size_t)(b * TTq + c * TC)) * Cq + h * Kq;
#pragma unroll
    for (int l = 0; l < 4; l++) {
        int lin = t + l * 256;
        int row = lin >> 4;
        int c4  = (lin & 15) * 4;
        *(float4*)&ks[row * Kq + c4] = *(const float4*)(kp + (size_t)row * Cq + c4);
        *(float4*)&vs[row * Kq + c4] = *(const float4*)(vp + (size_t)row * Cq + c4);
    }
    float dec = expf(-expf(td[h]));
    if (t == 0) {
        float p = 1.f;
        for (int i = 0; i < TC; i++) { pw[i] = p; p *= dec; }
    }
    __syncthreads();

    int tp = t >> 4, tq = t & 15;
    float acc[4][4];
#pragma unroll
    for (int i = 0; i < 4; i++)
#pragma unroll
        for (int j = 0; j < 4; j++) acc[i][j] = 0.f;

#pragma unroll 4
    for (int j = 0; j < TC; j++) {
        float w  = pw[TC - 1 - j];
        float4 a  = *(const float4*)&ks[j * Kq + tp * 4];
        float4 bb = *(const float4*)&vs[j * Kq + tq * 4];
        float a0 = a.x * w, a1 = a.y * w, a2 = a.z * w, a3 = a.w * w;
        acc[0][0] += a0 * bb.x; acc[0][1] += a0 * bb.y; acc[0][2] += a0 * bb.z; acc[0][3] += a0 * bb.w;
        acc[1][0] += a1 * bb.x; acc[1][1] += a1 * bb.y; acc[1][2] += a1 * bb.z; acc[1][3] += a1 * bb.w;
        acc[2][0] += a2 * bb.x; acc[2][1] += a2 * bb.y; acc[2][2] += a2 * bb.z; acc[2][3] += a2 * bb.w;
        acc[3][0] += a3 * bb.x; acc[3][1] += a3 * bb.y; acc[3][2] += a3 * bb.z; acc[3][3] += a3 * bb.w;
    }
    float* Ap = g_A + (size_t)cb * (Kq * Kq);
#pragma unroll
    for (int i = 0; i < 4; i++)
        *(float4*)&Ap[(tp * 4 + i) * Kq + tq * 4] =
            make_float4(acc[i][0], acc[i][1], acc[i][2], acc[i][3]);
}

// ---------------- 4) Phase B: sequential state scan per (b,h) ---------------
__global__ __launch_bounds__(256)
void phaseB_kernel(const float* __restrict__ td)
{
    int bh = blockIdx.x;
    int h = bh & (Hq - 1);
    int b = bh >> 4;
    int t = threadIdx.x;

    float dec = expf(-expf(td[h]));
    float ws = 1.f;
    for (int i = 0; i < TC; i++) ws *= dec;

    float S[16];
#pragma unroll
    for (int i = 0; i < 16; i++) S[i] = 0.f;

    for (int c = 0; c < NC; c++) {
        size_t base = ((size_t)(c * Bq + b) * Hq + h) * (Kq * Kq);
#pragma unroll
        for (int i = 0; i < 16; i++) {
            int e = t + i * 256;
            g_S[base + e] = S[i];
            S[i] = ws * S[i] + g_A[base + e];
        }
    }
}

// ---------------- 5) Phase C: per-chunk output (T=64) ------------------------
// smem: rT[64][68], kT[64][68], vs[64][64], Ss[64][64], att[64][65], pw[64]
#define PC_SMEM ((64*68*2 + 64*64*2 + 64*65 + 64) * 4)   // 84480 B

__global__ __launch_bounds__(256)
void phaseC_kernel(const float* __restrict__ rbuf, const float* __restrict__ kbuf,
                   const float* __restrict__ vbuf, const float* __restrict__ td,
                   const float* __restrict__ tf, float* __restrict__ xo)
{
    extern __shared__ float sm[];
    float* rT  = sm;                 // [64 p][68] (k-major)
    float* kT  = rT + 64 * 68;
    float* vs  = kT + 64 * 68;       // [64 j][64 q]
    float* Ss  = vs + 64 * 64;       // [64 p][64 q]
    float* att = Ss + 64 * 64;       // [64][65]
    float* pw  = att + 64 * 65;

    int cb = blockIdx.x;
    int h  = cb & (Hq - 1);
    int b  = (cb >> 4) & (Bq - 1);
    int c  = cb >> 6;
    int t  = threadIdx.x;

    const float* rp = rbuf + ((size_t)(b * TTq + c * TC)) * Cq + h * Kq;
    const float* kp = kbuf + ((size_t)(b * TTq + c * TC)) * Cq + h * Kq;
    const float* vp = vbuf + ((size_t)(b * TTq + c * TC)) * Cq + h * Kq;

#pragma unroll
    for (int l = 0; l < 4; l++) {
        int lin = t + l * 256;
        int row = lin >> 4;
        int c4  = (lin & 15) * 4;
        float4 rv = *(const float4*)(rp + (size_t)row * Cq + c4);
        float4 kv = *(const float4*)(kp + (size_t)row * Cq + c4);
        float4 vv = *(const float4*)(vp + (size_t)row * Cq + c4);
        rT[(c4 + 0) * 68 + row] = rv.x; rT[(c4 + 1) * 68 + row] = rv.y;
        rT[(c4 + 2) * 68 + row] = rv.z; rT[(c4 + 3) * 68 + row] = rv.w;
        kT[(c4 + 0) * 68 + row] = kv.x; kT[(c4 + 1) * 68 + row] = kv.y;
        kT[(c4 + 2) * 68 + row] = kv.z; kT[(c4 + 3) * 68 + row] = kv.w;
        *(float4*)&vs[row * Kq + c4] = vv;
    }
    {
        const float* Sp = g_S + (size_t)cb * (Kq * Kq);
#pragma unroll
        for (int l = 0; l < 4; l++) {
            int lin = t + l * 256;
            *(float4*)&Ss[lin * 4] = *(const float4*)(Sp + lin * 4);
        }
    }
    float dec = expf(-expf(td[h]));
    float u   = tf[h];
    if (t == 0) {
        float p = 1.f;
        for (int i = 0; i < TC; i++) { pw[i] = p; p *= dec; }
    }
    __syncthreads();

    // att[i][j] = (r_i . k_j) * w_mat[i][j], 4x4 tiles, band tj <= (ti|1)
    // (band covers every tile the causal consumer below reads; gi<gj gets w=0)
    {
        int ti = t >> 4, tj = t & 15;
        int i0 = ti * 4, j0 = tj * 4;
        if (tj <= (ti | 1)) {
            float acc[4][4];
#pragma unroll
            for (int i = 0; i < 4; i++)
#pragma unroll
                for (int j = 0; j < 4; j++) acc[i][j] = 0.f;
#pragma unroll 4
            for (int k = 0; k < Kq; k++) {
                float4 a = *(const float4*)&rT[k * 68 + i0];
                float4 bb = *(const float4*)&kT[k * 68 + j0];
                float av[4] = { a.x, a.y, a.z, a.w };
                float bv[4] = { bb.x, bb.y, bb.z, bb.w };
#pragma unroll
                for (int i = 0; i < 4; i++)
#pragma unroll
                    for (int j = 0; j < 4; j++) acc[i][j] += av[i] * bv[j];
            }
#pragma unroll
            for (int i = 0; i < 4; i++)
#pragma unroll
                for (int j = 0; j < 4; j++) {
                    int gi = i0 + i, gj = j0 + j;
                    float ww = (gi > gj) ? pw[gi - gj - 1] : ((gi == gj) ? u : 0.f);
                    att[gi * 65 + gj] = acc[i][j] * ww;
                }
        }
    }
    __syncthreads();

    // out[i][q] = sum_j att[i][j] v[j][q] + (sum_p r[i][p] S[p][q]) * wb[i]
    {
        int i0 = (t >> 5) * 8;          // warp-uniform row group
        int q0 = (t & 31) * 2;
        float acc[8][2];
#pragma unroll
        for (int i = 0; i < 8; i++) { acc[i][0] = 0.f; acc[i][1] = 0.f; }

#pragma unroll 4
        for (int p = 0; p < Kq; p++) {
            float2 s2 = *(const float2*)&Ss[p * Kq + q0];
            const float* rr = &rT[p * 68 + i0];
#pragma unroll
            for (int i = 0; i < 8; i++) {
                float a = rr[i];
                acc[i][0] += a * s2.x; acc[i][1] += a * s2.y;
            }
        }
#pragma unroll
        for (int i = 0; i < 8; i++) {
            float wbi = pw[i0 + i];
            acc[i][0] *= wbi; acc[i][1] *= wbi;
        }
        // causal: rows [i0, i0+8) only consume att columns j < i0+8
        int jmax = i0 + 8;
#pragma unroll 2
        for (int j = 0; j < jmax; j++) {
            float2 v2 = *(const float2*)&vs[j * Kq + q0];
#pragma unroll
            for (int i = 0; i < 8; i++) {
                float aij = att[(i0 + i) * 65 + j];
                acc[i][0] += aij * v2.x; acc[i][1] += aij * v2.y;
            }
        }
        float* op = xo + ((size_t)(b * TTq + c * TC)) * Cq + h * Kq + q0;
#pragma unroll
        for (int i = 0; i < 8; i++)
            *(float2*)(op + (size_t)(i0 + i) * Cq) = make_float2(acc[i][0], acc[i][1]);
    }
}

// ---------------- 6) GroupNorm + SiLU gate + bf16 split ---------------------
__global__ __launch_bounds__(256)
void gnorm_gate_kernel(const float* __restrict__ lnw, const float* __restrict__ lnb)
{
    int gwarp = (blockIdx.x * 256 + threadIdx.x) >> 5;
    int lane  = threadIdx.x & 31;
    int h = gwarp & (Hq - 1);
    size_t base = (size_t)gwarp * Kq + lane * 2;

    float2 xo2 = *(const float2*)(g_xo + base);
    float y0 = xo2.x * 0.125f, y1 = xo2.y * 0.125f;
    float s1 = y0 + y1, s2 = y0 * y0 + y1 * y1;
#pragma unroll
    for (int o = 16; o; o >>= 1) {
        s1 += __shfl_xor_sync(0xffffffffu, s1, o);
        s2 += __shfl_xor_sync(0xffffffffu, s2, o);
    }
    float mean = s1 * (1.f / 64.f);
    float var  = s2 * (1.f / 64.f) - mean * mean;
    float rstd = rsqrtf(var + 1e-5f);

    int ci = h * Kq + lane * 2;
    float w0 = lnw[ci], w1 = lnw[ci + 1];
    float b0 = lnb[ci], b1 = lnb[ci + 1];

    float2 g2 = *(const float2*)(g_o4 + (size_t)3 * BT * Cq + base);
    float sg0 = g2.x / (1.f + expf(-g2.x));
    float sg1 = g2.y / (1.f + expf(-g2.y));

    float o0 = ((y0 - mean) * rstd * w0 + b0) * sg0;
    float o1 = ((y1 - mean) * rstd * w1 + b1) * sg1;

    __nv_bfloat16 h0 = __float2bfloat16(o0), h1 = __float2bfloat16(o1);
    __nv_bfloat16 l0 = __float2bfloat16(o0 - __bfloat162float(h0));
    __nv_bfloat16 l1 = __float2bfloat16(o1 - __bfloat162float(h1));
    __nv_bfloat162 hv; hv.x = h0; hv.y = h1;
    __nv_bfloat162 lv; lv.x = l0; lv.y = l1;
    *(__nv_bfloat162*)(g_yh + base) = hv;
    *(__nv_bfloat162*)(g_yl + base) = lv;
}

// ---------------- launcher ---------------------------------------------------
extern "C" void kernel_launch(void* const* d_in, const int* in_sizes, int n_in,
                              void* d_out, int out_size)
{
    (void)in_sizes; (void)n_in; (void)out_size;
    const float* x   = (const float*)d_in[0];
    const float* tmk = (const float*)d_in[1];
    const float* tmv = (const float*)d_in[2];
    const float* tmr = (const float*)d_in[3];
    const float* tmg = (const float*)d_in[4];
    const float* td  = (const float*)d_in[5];
    const float* tf  = (const float*)d_in[6];
    const float* Wr  = (const float*)d_in[7];
    const float* Wk  = (const float*)d_in[8];
    const float* Wv  = (const float*)d_in[9];
    const float* Wg  = (const float*)d_in[10];
    const float* Wo  = (const float*)d_in[11];
    const float* lnw = (const float*)d_in[12];
    const float* lnb = (const float*)d_in[13];
    float* out = (float*)d_out;

    __nv_bfloat16 *p_xh, *p_xl, *p_yh, *p_yl, *p_Wh, *p_Wl;
    float *p_o4, *p_xo;
    cudaGetSymbolAddress((void**)&p_xh, g_xh);
    cudaGetSymbolAddress((void**)&p_xl, g_xl);
    cudaGetSymbolAddress((void**)&p_yh, g_yh);
    cudaGetSymbolAddress((void**)&p_yl, g_yl);
    cudaGetSymbolAddress((void**)&p_Wh, g_Wh);
    cudaGetSymbolAddress((void**)&p_Wl, g_Wl);
    cudaGetSymbolAddress((void**)&p_o4, g_o4);
    cudaGetSymbolAddress((void**)&p_xo, g_xo);

    cudaFuncSetAttribute(gemm_hmma, cudaFuncAttributeMaxDynamicSharedMemorySize, GSMEM);
    cudaFuncSetAttribute(phaseC_kernel, cudaFuncAttributeMaxDynamicSharedMemorySize, PC_SMEM);

    mix_split_kernel<<<(BT * Cq) / 4 / 256, 256>>>(x, tmr, tmk, tmv, tmg);

    dim3 wgrid((Cq * Cq) / 4 / 256, 5);
    wsplit5_kernel<<<wgrid, 256>>>(Wr, Wk, Wv, Wg, Wo, p_Wh, p_Wl);

    // fused r,k,v,g GEMMs: 4096 tile-jobs
    gemm_hmma<<<GGRID, 256, GSMEM>>>(p_xh, p_xl, p_Wh, p_Wl, p_o4, 4096);

    float* p_r = p_o4 + (size_t)0 * BT * Cq;
    float* p_k = p_o4 + (size_t)1 * BT * Cq;
    float* p_v = p_o4 + (size_t)2 * BT * Cq;

    phaseA_kernel<<<NC * Bq * Hq, 256>>>(p_k, p_v, td);
    phaseB_kernel<<<Bq * Hq, 256>>>(td);
    phaseC_kernel<<<NC * Bq * Hq, 256, PC_SMEM>>>(p_r, p_k, p_v, td, tf, p_xo);

    gnorm_gate_kernel<<<(BT * Hq) / 8, 256>>>(lnw, lnb);

    // output GEMM: 1024 jobs against the Wo slice
    gemm_hmma<<<GGRID, 256, GSMEM>>>(p_yh, p_yl,
                                     p_Wh + (size_t)4 * Cq * Cq,
                                     p_Wl + (size_t)4 * Cq * Cq, out, 1024);
}

// round 15
// speedup vs baseline: 1.1505x; 1.1505x over previous
#include <cuda_runtime.h>
#include <cuda_bf16.h>
#include <math.h>
#include <stdint.h>

// Problem constants
#define Bq   4
#define TTq  4096
#define Cq   1024
#define Hq   16
#define Kq   64
#define TC   64                   // attention chunk length
#define NC   (TTq / TC)           // 64 chunks
#define BT   (Bq * TTq)           // 16384 rows

// ---------------- scratch (static device arrays; no allocation) -------------
// activation hi/lo splits, 4 slices: r,k,v,g
__device__ __nv_bfloat16 g_xh[4 * BT * Cq], g_xl[4 * BT * Cq];
__device__ __nv_bfloat16 g_yh[BT * Cq], g_yl[BT * Cq];
__device__ __nv_bfloat16 g_Wh[5 * Cq * Cq], g_Wl[5 * Cq * Cq];
__device__ float g_o4[4 * BT * Cq];          // r,k,v,g GEMM outputs
__device__ float g_xo[BT * Cq];
__device__ float g_A [NC * Bq * Hq * Kq * Kq];
__device__ float g_S [NC * Bq * Hq * Kq * Kq];

// ---------------- PTX helpers (baseline ISA only) ----------------------------
__device__ __forceinline__ uint32_t smem_u32(const void* p) {
    uint32_t a;
    asm("{ .reg .u64 t; cvta.to.shared.u64 t, %1; cvt.u32.u64 %0, t; }"
        : "=r"(a) : "l"(p));
    return a;
}
__device__ __forceinline__ void cp_async16(uint32_t saddr, const void* gaddr) {
    asm volatile("cp.async.cg.shared.global [%0], [%1], 16;"
                 :: "r"(saddr), "l"(gaddr) : "memory");
}
__device__ __forceinline__ void cp_commit() {
    asm volatile("cp.async.commit_group;" ::: "memory");
}
__device__ __forceinline__ void ldm_x4(uint32_t* r, uint32_t addr) {
    asm volatile("ldmatrix.sync.aligned.m8n8.x4.shared.b16 {%0,%1,%2,%3}, [%4];"
                 : "=r"(r[0]), "=r"(r[1]), "=r"(r[2]), "=r"(r[3]) : "r"(addr));
}
__device__ __forceinline__ void mma_bf16(float* c, const uint32_t* a,
                                         uint32_t b0, uint32_t b1) {
    asm volatile(
        "mma.sync.aligned.m16n8k16.row.col.f32.bf16.bf16.f32 "
        "{%0,%1,%2,%3}, {%4,%5,%6,%7}, {%8,%9}, {%0,%1,%2,%3};"
        : "+f"(c[0]), "+f"(c[1]), "+f"(c[2]), "+f"(c[3])
        : "r"(a[0]), "r"(a[1]), "r"(a[2]), "r"(a[3]), "r"(b0), "r"(b1));
}

// ---------------- 1) time-shift mixing + bf16 hi/lo split -------------------
__device__ __forceinline__ void split_store(float4 o, __nv_bfloat16* hp, __nv_bfloat16* lp) {
    __nv_bfloat16 h0 = __float2bfloat16(o.x), h1 = __float2bfloat16(o.y);
    __nv_bfloat16 h2 = __float2bfloat16(o.z), h3 = __float2bfloat16(o.w);
    __nv_bfloat16 l0 = __float2bfloat16(o.x - __bfloat162float(h0));
    __nv_bfloat16 l1 = __float2bfloat16(o.y - __bfloat162float(h1));
    __nv_bfloat16 l2 = __float2bfloat16(o.z - __bfloat162float(h2));
    __nv_bfloat16 l3 = __float2bfloat16(o.w - __bfloat162float(h3));
    __nv_bfloat162 a; a.x = h0; a.y = h1;
    __nv_bfloat162 b; b.x = h2; b.y = h3;
    *(__nv_bfloat162*)(hp)     = a;
    *(__nv_bfloat162*)(hp + 2) = b;
    a.x = l0; a.y = l1; b.x = l2; b.y = l3;
    *(__nv_bfloat162*)(lp)     = a;
    *(__nv_bfloat162*)(lp + 2) = b;
}

__global__ __launch_bounds__(256)
void mix_split_kernel(const float* __restrict__ x,
                      const float* __restrict__ tmr, const float* __restrict__ tmk,
                      const float* __restrict__ tmv, const float* __restrict__ tmg)
{
    int idx = blockIdx.x * 256 + threadIdx.x;
    int e = idx * 4;
    int c = e & (Cq - 1);
    int bt = e >> 10;
    int tt = bt & (TTq - 1);

    float4 xc = *(const float4*)(x + e);
    float4 xp = make_float4(0.f, 0.f, 0.f, 0.f);
    if (tt != 0) xp = *(const float4*)(x + e - Cq);

    float4 m, o;
    m = *(const float4*)(tmr + c);
    o.x = xc.x * m.x + xp.x * (1.f - m.x); o.y = xc.y * m.y + xp.y * (1.f - m.y);
    o.z = xc.z * m.z + xp.z * (1.f - m.z); o.w = xc.w * m.w + xp.w * (1.f - m.w);
    split_store(o, g_xh + (size_t)0 * BT * Cq + e, g_xl + (size_t)0 * BT * Cq + e);
    m = *(const float4*)(tmk + c);
    o.x = xc.x * m.x + xp.x * (1.f - m.x); o.y = xc.y * m.y + xp.y * (1.f - m.y);
    o.z = xc.z * m.z + xp.z * (1.f - m.z); o.w = xc.w * m.w + xp.w * (1.f - m.w);
    split_store(o, g_xh + (size_t)1 * BT * Cq + e, g_xl + (size_t)1 * BT * Cq + e);
    m = *(const float4*)(tmv + c);
    o.x = xc.x * m.x + xp.x * (1.f - m.x); o.y = xc.y * m.y + xp.y * (1.f - m.y);
    o.z = xc.z * m.z + xp.z * (1.f - m.z); o.w = xc.w * m.w + xp.w * (1.f - m.w);
    split_store(o, g_xh + (size_t)2 * BT * Cq + e, g_xl + (size_t)2 * BT * Cq + e);
    m = *(const float4*)(tmg + c);
    o.x = xc.x * m.x + xp.x * (1.f - m.x); o.y = xc.y * m.y + xp.y * (1.f - m.y);
    o.z = xc.z * m.z + xp.z * (1.f - m.z); o.w = xc.w * m.w + xp.w * (1.f - m.w);
    split_store(o, g_xh + (size_t)3 * BT * Cq + e, g_xl + (size_t)3 * BT * Cq + e);
}

__global__ __launch_bounds__(256)
void wsplit5_kernel(const float* __restrict__ W0, const float* __restrict__ W1,
                    const float* __restrict__ W2, const float* __restrict__ W3,
                    const float* __restrict__ W4,
                    __nv_bfloat16* __restrict__ Wh, __nv_bfloat16* __restrict__ Wl)
{
    int m = blockIdx.y;
    const float* W = (m == 0) ? W0 : (m == 1) ? W1 : (m == 2) ? W2 : (m == 3) ? W3 : W4;
    int e = (blockIdx.x * 256 + threadIdx.x) * 4;
    float4 w = *(const float4*)(W + e);
    split_store(w, Wh + (size_t)m * Cq * Cq + e, Wl + (size_t)m * Cq * Cq + e);
}

// ---------------- 2) bf16x3 HMMA GEMM (R12-proven: 2-stage, occ 2) ----------
// C = Ah*Wh^T + Ah*Wl^T + Al*Wh^T; blockIdx.y = g*128 + bm (g selects slice).
// CTA tile 128x128, KB=32/stage; stage holds Ah,Al,Wh,Wl tiles (40KB);
// 2-stage cp.async pipeline in dynamic smem (80KB), 2 CTAs/SM.
// smem rows: 32 bf16 (64B) + 16B pad = 80B pitch -> conflict-free ldmatrix.
#define KB      32
#define TILE_B  10240                    // 128 rows * 80B
#define STG4    (4 * TILE_B)             // 40960: Ah|Al|Wh|Wl
#define GSMEM   (2 * STG4)               // 81920
#define NKB     32                       // 1024 / KB

__global__ __launch_bounds__(256, 2)
void gemm_hmma(const __nv_bfloat16* __restrict__ AhB,
               const __nv_bfloat16* __restrict__ AlB,
               const __nv_bfloat16* __restrict__ WhB,
               const __nv_bfloat16* __restrict__ WlB,
               float* __restrict__ CB)
{
    extern __shared__ __align__(16) char smem[];
    uint32_t sb = smem_u32(smem);

    int t = threadIdx.x;
    int w = t >> 5, lane = t & 31;
    int wm = w >> 2;            // 0..1  (64-row slab)
    int wn = w & 3;             // 0..3  (32-col slab)
    int g  = blockIdx.y >> 7;
    int bm = blockIdx.y & 127;
    int bn = blockIdx.x;

    const __nv_bfloat16* Ah = AhB + (size_t)g * BT * Cq;
    const __nv_bfloat16* Al = AlB + (size_t)g * BT * Cq;
    const __nv_bfloat16* Wh = WhB + (size_t)g * Cq * Cq;
    const __nv_bfloat16* Wl = WlB + (size_t)g * Cq * Cq;
    float* Cmat = CB + (size_t)g * BT * Cq;

    // cp.async geometry: per stage, per thread: 2 chunks per tile x 4 tiles
    uint32_t so[2]; size_t a_go[2], b_go[2];
#pragma unroll
    for (int i = 0; i < 2; i++) {
        int lin = t + i * 256;
        int row = lin >> 2, c16 = lin & 3;
        so[i]   = (uint32_t)(row * 80 + c16 * 16);
        a_go[i] = (size_t)(bm * 128 + row) * Cq + c16 * 8;
        b_go[i] = (size_t)(bn * 128 + row) * Cq + c16 * 8;
    }

    // ldmatrix per-lane base offsets (within one tile)
    int lr = lane & 7, sel = lane >> 3;
    uint32_t a_lb = (uint32_t)((wm * 64 + lr + (sel & 1) * 8) * 80 + ((sel >> 1) & 1) * 16);
    uint32_t b_lb = (uint32_t)((wn * 32 + lr + (sel >> 1) * 8) * 80 + (sel & 1) * 16);

    float C[4][4][4];
#pragma unroll
    for (int i = 0; i < 4; i++)
#pragma unroll
        for (int j = 0; j < 4; j++)
#pragma unroll
            for (int q = 0; q < 4; q++) C[i][j][q] = 0.f;

    // prologue: stage 0 <- kb 0
    {
        uint32_t st = sb;
#pragma unroll
        for (int i = 0; i < 2; i++) {
            cp_async16(st + so[i],              Ah + a_go[i]);
            cp_async16(st + TILE_B + so[i],     Al + a_go[i]);
            cp_async16(st + 2 * TILE_B + so[i], Wh + b_go[i]);
            cp_async16(st + 3 * TILE_B + so[i], Wl + b_go[i]);
        }
        cp_commit();
    }

    for (int kb = 0; kb < NKB; kb++) {
        if (kb + 1 < NKB) {
            int k0 = (kb + 1) * KB;
            uint32_t st = sb + ((kb + 1) & 1) * STG4;
#pragma unroll
            for (int i = 0; i < 2; i++) {
                cp_async16(st + so[i],              Ah + a_go[i] + k0);
                cp_async16(st + TILE_B + so[i],     Al + a_go[i] + k0);
                cp_async16(st + 2 * TILE_B + so[i], Wh + b_go[i] + k0);
                cp_async16(st + 3 * TILE_B + so[i], Wl + b_go[i] + k0);
            }
            cp_commit();
            asm volatile("cp.async.wait_group 1;" ::: "memory");
        } else {
            asm volatile("cp.async.wait_group 0;" ::: "memory");
        }
        __syncthreads();

        uint32_t base = sb + (kb & 1) * STG4;
#pragma unroll
        for (int s = 0; s < 2; s++) {
            uint32_t aH[4][4], bH[2][4], bL[2][4];
            // combo 1: Ah * Wh
#pragma unroll
            for (int mt = 0; mt < 4; mt++)
                ldm_x4(aH[mt], base + a_lb + (uint32_t)(mt * 16 * 80 + s * 32));
#pragma unroll
            for (int gg = 0; gg < 2; gg++)
                ldm_x4(bH[gg], base + 2 * TILE_B + b_lb + (uint32_t)(gg * 16 * 80 + s * 32));
#pragma unroll
            for (int mt = 0; mt < 4; mt++)
#pragma unroll
                for (int gg = 0; gg < 2; gg++) {
                    mma_bf16(C[mt][2 * gg],     aH[mt], bH[gg][0], bH[gg][1]);
                    mma_bf16(C[mt][2 * gg + 1], aH[mt], bH[gg][2], bH[gg][3]);
                }
            // combo 2: Ah * Wl  (reuse aH)
#pragma unroll
            for (int gg = 0; gg < 2; gg++)
                ldm_x4(bL[gg], base + 3 * TILE_B + b_lb + (uint32_t)(gg * 16 * 80 + s * 32));
#pragma unroll
            for (int mt = 0; mt < 4; mt++)
#pragma unroll
                for (int gg = 0; gg < 2; gg++) {
                    mma_bf16(C[mt][2 * gg],     aH[mt], bL[gg][0], bL[gg][1]);
                    mma_bf16(C[mt][2 * gg + 1], aH[mt], bL[gg][2], bL[gg][3]);
                }
            // combo 3: Al * Wh  (reuse bH)
            uint32_t aL[4][4];
#pragma unroll
            for (int mt = 0; mt < 4; mt++)
                ldm_x4(aL[mt], base + TILE_B + a_lb + (uint32_t)(mt * 16 * 80 + s * 32));
#pragma unroll
            for (int mt = 0; mt < 4; mt++)
#pragma unroll
                for (int gg = 0; gg < 2; gg++) {
                    mma_bf16(C[mt][2 * gg],     aL[mt], bH[gg][0], bH[gg][1]);
                    mma_bf16(C[mt][2 * gg + 1], aL[mt], bH[gg][2], bH[gg][3]);
                }
        }
        __syncthreads();
    }

    // epilogue: direct fp32 stores
    int row0 = bm * 128 + wm * 64 + (lane >> 2);
    int col0 = bn * 128 + wn * 32 + (lane & 3) * 2;
#pragma unroll
    for (int mt = 0; mt < 4; mt++) {
#pragma unroll
        for (int nt = 0; nt < 4; nt++) {
            float* p0 = Cmat + (size_t)(row0 + mt * 16) * Cq + col0 + nt * 8;
            float* p1 = p0 + 8 * Cq;
            *(float2*)p0 = make_float2(C[mt][nt][0], C[mt][nt][1]);
            *(float2*)p1 = make_float2(C[mt][nt][2], C[mt][nt][3]);
        }
    }
}

// ---------------- 3) Phase A: A_c = k^T diag(wk) v per chunk-head (T=64) ----
__global__ __launch_bounds__(256)
void phaseA_kernel(const float* __restrict__ kbuf, const float* __restrict__ vbuf,
                   const float* __restrict__ td)
{
    __shared__ float ks[TC * Kq], vs[TC * Kq], pw[TC];

    int cb = blockIdx.x;           // ((c*B + b)*H + h)
    int h  = cb & (Hq - 1);
    int b  = (cb >> 4) & (Bq - 1);
    int c  = cb >> 6;
    int t  = threadIdx.x;

    const float* kp = kbuf + ((size_t)(b * TTq + c * TC)) * Cq + h * Kq;
    const float* vp = vbuf + ((size_t)(b * TTq + c * TC)) * Cq + h * Kq;
#pragma unroll
    for (int l = 0; l < 4; l++) {
        int lin = t + l * 256;
        int row = lin >> 4;
        int c4  = (lin & 15) * 4;
        *(float4*)&ks[row * Kq + c4] = *(const float4*)(kp + (size_t)row * Cq + c4);
        *(float4*)&vs[row * Kq + c4] = *(const float4*)(vp + (size_t)row * Cq + c4);
    }
    float dec = expf(-expf(td[h]));
    if (t == 0) {
        float p = 1.f;
        for (int i = 0; i < TC; i++) { pw[i] = p; p *= dec; }
    }
    __syncthreads();

    int tp = t >> 4, tq = t & 15;
    float acc[4][4];
#pragma unroll
    for (int i = 0; i < 4; i++)
#pragma unroll
        for (int j = 0; j < 4; j++) acc[i][j] = 0.f;

#pragma unroll 4
    for (int j = 0; j < TC; j++) {
        float w  = pw[TC - 1 - j];
        float4 a  = *(const float4*)&ks[j * Kq + tp * 4];
        float4 bb = *(const float4*)&vs[j * Kq + tq * 4];
        float a0 = a.x * w, a1 = a.y * w, a2 = a.z * w, a3 = a.w * w;
        acc[0][0] += a0 * bb.x; acc[0][1] += a0 * bb.y; acc[0][2] += a0 * bb.z; acc[0][3] += a0 * bb.w;
        acc[1][0] += a1 * bb.x; acc[1][1] += a1 * bb.y; acc[1][2] += a1 * bb.z; acc[1][3] += a1 * bb.w;
        acc[2][0] += a2 * bb.x; acc[2][1] += a2 * bb.y; acc[2][2] += a2 * bb.z; acc[2][3] += a2 * bb.w;
        acc[3][0] += a3 * bb.x; acc[3][1] += a3 * bb.y; acc[3][2] += a3 * bb.z; acc[3][3] += a3 * bb.w;
    }
    float* Ap = g_A + (size_t)cb * (Kq * Kq);
#pragma unroll
    for (int i = 0; i < 4; i++)
        *(float4*)&Ap[(tp * 4 + i) * Kq + tq * 4] =
            make_float4(acc[i][0], acc[i][1], acc[i][2], acc[i][3]);
}

// ---------------- 4) Phase B: sequential state scan per (b,h) ---------------
__global__ __launch_bounds__(256)
void phaseB_kernel(const float* __restrict__ td)
{
    int bh = blockIdx.x;
    int h = bh & (Hq - 1);
    int b = bh >> 4;
    int t = threadIdx.x;

    float dec = expf(-expf(td[h]));
    float ws = 1.f;
    for (int i = 0; i < TC; i++) ws *= dec;

    float S[16];
#pragma unroll
    for (int i = 0; i < 16; i++) S[i] = 0.f;

    for (int c = 0; c < NC; c++) {
        size_t base = ((size_t)(c * Bq + b) * Hq + h) * (Kq * Kq);
#pragma unroll
        for (int i = 0; i < 16; i++) {
            int e = t + i * 256;
            g_S[base + e] = S[i];
            S[i] = ws * S[i] + g_A[base + e];
        }
    }
}

// ---------------- 5) Phase C: per-chunk output (T=64) ------------------------
// smem: rT[64][68], kT[64][68], vs[64][64], Ss[64][64], att[64][65], pw[64]
#define PC_SMEM ((64*68*2 + 64*64*2 + 64*65 + 64) * 4)   // 84480 B

__global__ __launch_bounds__(256)
void phaseC_kernel(const float* __restrict__ rbuf, const float* __restrict__ kbuf,
                   const float* __restrict__ vbuf, const float* __restrict__ td,
                   const float* __restrict__ tf, float* __restrict__ xo)
{
    extern __shared__ float sm[];
    float* rT  = sm;                 // [64 p][68] (k-major)
    float* kT  = rT + 64 * 68;
    float* vs  = kT + 64 * 68;       // [64 j][64 q]
    float* Ss  = vs + 64 * 64;       // [64 p][64 q]
    float* att = Ss + 64 * 64;       // [64][65]
    float* pw  = att + 64 * 65;

    int cb = blockIdx.x;
    int h  = cb & (Hq - 1);
    int b  = (cb >> 4) & (Bq - 1);
    int c  = cb >> 6;
    int t  = threadIdx.x;

    const float* rp = rbuf + ((size_t)(b * TTq + c * TC)) * Cq + h * Kq;
    const float* kp = kbuf + ((size_t)(b * TTq + c * TC)) * Cq + h * Kq;
    const float* vp = vbuf + ((size_t)(b * TTq + c * TC)) * Cq + h * Kq;

#pragma unroll
    for (int l = 0; l < 4; l++) {
        int lin = t + l * 256;
        int row = lin >> 4;
        int c4  = (lin & 15) * 4;
        float4 rv = *(const float4*)(rp + (size_t)row * Cq + c4);
        float4 kv = *(const float4*)(kp + (size_t)row * Cq + c4);
        float4 vv = *(const float4*)(vp + (size_t)row * Cq + c4);
        rT[(c4 + 0) * 68 + row] = rv.x; rT[(c4 + 1) * 68 + row] = rv.y;
        rT[(c4 + 2) * 68 + row] = rv.z; rT[(c4 + 3) * 68 + row] = rv.w;
        kT[(c4 + 0) * 68 + row] = kv.x; kT[(c4 + 1) * 68 + row] = kv.y;
        kT[(c4 + 2) * 68 + row] = kv.z; kT[(c4 + 3) * 68 + row] = kv.w;
        *(float4*)&vs[row * Kq + c4] = vv;
    }
    {
        const float* Sp = g_S + (size_t)cb * (Kq * Kq);
#pragma unroll
        for (int l = 0; l < 4; l++) {
            int lin = t + l * 256;
            *(float4*)&Ss[lin * 4] = *(const float4*)(Sp + lin * 4);
        }
    }
    float dec = expf(-expf(td[h]));
    float u   = tf[h];
    if (t == 0) {
        float p = 1.f;
        for (int i = 0; i < TC; i++) { pw[i] = p; p *= dec; }
    }
    __syncthreads();

    // att[i][j] = (r_i . k_j) * w_mat[i][j], 4x4 tiles, band tj <= (ti|1)
    {
        int ti = t >> 4, tj = t & 15;
        int i0 = ti * 4, j0 = tj * 4;
        if (tj <= (ti | 1)) {
            float acc[4][4];
#pragma unroll
            for (int i = 0; i < 4; i++)
#pragma unroll
                for (int j = 0; j < 4; j++) acc[i][j] = 0.f;
#pragma unroll 4
            for (int k = 0; k < Kq; k++) {
                float4 a = *(const float4*)&rT[k * 68 + i0];
                float4 bb = *(const float4*)&kT[k * 68 + j0];
                float av[4] = { a.x, a.y, a.z, a.w };
                float bv[4] = { bb.x, bb.y, bb.z, bb.w };
#pragma unroll
                for (int i = 0; i < 4; i++)
#pragma unroll
                    for (int j = 0; j < 4; j++) acc[i][j] += av[i] * bv[j];
            }
#pragma unroll
            for (int i = 0; i < 4; i++)
#pragma unroll
                for (int j = 0; j < 4; j++) {
                    int gi = i0 + i, gj = j0 + j;
                    float ww = (gi > gj) ? pw[gi - gj - 1] : ((gi == gj) ? u : 0.f);
                    att[gi * 65 + gj] = acc[i][j] * ww;
                }
        }
    }
    __syncthreads();

    // out[i][q] = sum_j att[i][j] v[j][q] + (sum_p r[i][p] S[p][q]) * wb[i]
    {
        int i0 = (t >> 5) * 8;          // warp-uniform row group
        int q0 = (t & 31) * 2;
        float acc[8][2];
#pragma unroll
        for (int i = 0; i < 8; i++) { acc[i][0] = 0.f; acc[i][1] = 0.f; }

#pragma unroll 4
        for (int p = 0; p < Kq; p++) {
            float2 s2 = *(const float2*)&Ss[p * Kq + q0];
            const float* rr = &rT[p * 68 + i0];
#pragma unroll
            for (int i = 0; i < 8; i++) {
                float a = rr[i];
                acc[i][0] += a * s2.x; acc[i][1] += a * s2.y;
            }
        }
#pragma unroll
        for (int i = 0; i < 8; i++) {
            float wbi = pw[i0 + i];
            acc[i][0] *= wbi; acc[i][1] *= wbi;
        }
        // causal: rows [i0, i0+8) only consume att columns j < i0+8
        int jmax = i0 + 8;
#pragma unroll 2
        for (int j = 0; j < jmax; j++) {
            float2 v2 = *(const float2*)&vs[j * Kq + q0];
#pragma unroll
            for (int i = 0; i < 8; i++) {
                float aij = att[(i0 + i) * 65 + j];
                acc[i][0] += aij * v2.x; acc[i][1] += aij * v2.y;
            }
        }
        float* op = xo + ((size_t)(b * TTq + c * TC)) * Cq + h * Kq + q0;
#pragma unroll
        for (int i = 0; i < 8; i++)
            *(float2*)(op + (size_t)(i0 + i) * Cq) = make_float2(acc[i][0], acc[i][1]);
    }
}

// ---------------- 6) GroupNorm + SiLU gate + bf16 split ---------------------
__global__ __launch_bounds__(256)
void gnorm_gate_kernel(const float* __restrict__ lnw, const float* __restrict__ lnb)
{
    int gwarp = (blockIdx.x * 256 + threadIdx.x) >> 5;
    int lane  = threadIdx.x & 31;
    int h = gwarp & (Hq - 1);
    size_t base = (size_t)gwarp * Kq + lane * 2;

    float2 xo2 = *(const float2*)(g_xo + base);
    float y0 = xo2.x * 0.125f, y1 = xo2.y * 0.125f;
    float s1 = y0 + y1, s2 = y0 * y0 + y1 * y1;
#pragma unroll
    for (int o = 16; o; o >>= 1) {
        s1 += __shfl_xor_sync(0xffffffffu, s1, o);
        s2 += __shfl_xor_sync(0xffffffffu, s2, o);
    }
    float mean = s1 * (1.f / 64.f);
    float var  = s2 * (1.f / 64.f) - mean * mean;
    float rstd = rsqrtf(var + 1e-5f);

    int ci = h * Kq + lane * 2;
    float w0 = lnw[ci], w1 = lnw[ci + 1];
    float b0 = lnb[ci], b1 = lnb[ci + 1];

    float2 g2 = *(const float2*)(g_o4 + (size_t)3 * BT * Cq + base);
    float sg0 = g2.x / (1.f + expf(-g2.x));
    float sg1 = g2.y / (1.f + expf(-g2.y));

    float o0 = ((y0 - mean) * rstd * w0 + b0) * sg0;
    float o1 = ((y1 - mean) * rstd * w1 + b1) * sg1;

    __nv_bfloat16 h0 = __float2bfloat16(o0), h1 = __float2bfloat16(o1);
    __nv_bfloat16 l0 = __float2bfloat16(o0 - __bfloat162float(h0));
    __nv_bfloat16 l1 = __float2bfloat16(o1 - __bfloat162float(h1));
    __nv_bfloat162 hv; hv.x = h0; hv.y = h1;
    __nv_bfloat162 lv; lv.x = l0; lv.y = l1;
    *(__nv_bfloat162*)(g_yh + base) = hv;
    *(__nv_bfloat162*)(g_yl + base) = lv;
}

// ---------------- launcher ---------------------------------------------------
extern "C" void kernel_launch(void* const* d_in, const int* in_sizes, int n_in,
                              void* d_out, int out_size)
{
    (void)in_sizes; (void)n_in; (void)out_size;
    const float* x   = (const float*)d_in[0];
    const float* tmk = (const float*)d_in[1];
    const float* tmv = (const float*)d_in[2];
    const float* tmr = (const float*)d_in[3];
    const float* tmg = (const float*)d_in[4];
    const float* td  = (const float*)d_in[5];
    const float* tf  = (const float*)d_in[6];
    const float* Wr  = (const float*)d_in[7];
    const float* Wk  = (const float*)d_in[8];
    const float* Wv  = (const float*)d_in[9];
    const float* Wg  = (const float*)d_in[10];
    const float* Wo  = (const float*)d_in[11];
    const float* lnw = (const float*)d_in[12];
    const float* lnb = (const float*)d_in[13];
    float* out = (float*)d_out;

    __nv_bfloat16 *p_xh, *p_xl, *p_yh, *p_yl, *p_Wh, *p_Wl;
    float *p_o4, *p_xo;
    cudaGetSymbolAddress((void**)&p_xh, g_xh);
    cudaGetSymbolAddress((void**)&p_xl, g_xl);
    cudaGetSymbolAddress((void**)&p_yh, g_yh);
    cudaGetSymbolAddress((void**)&p_yl, g_yl);
    cudaGetSymbolAddress((void**)&p_Wh, g_Wh);
    cudaGetSymbolAddress((void**)&p_Wl, g_Wl);
    cudaGetSymbolAddress((void**)&p_o4, g_o4);
    cudaGetSymbolAddress((void**)&p_xo, g_xo);

    cudaFuncSetAttribute(gemm_hmma, cudaFuncAttributeMaxDynamicSharedMemorySize, GSMEM);
    cudaFuncSetAttribute(phaseC_kernel, cudaFuncAttributeMaxDynamicSharedMemorySize, PC_SMEM);

    mix_split_kernel<<<(BT * Cq) / 4 / 256, 256>>>(x, tmr, tmk, tmv, tmg);

    dim3 wgrid((Cq * Cq) / 4 / 256, 5);
    wsplit5_kernel<<<wgrid, 256>>>(Wr, Wk, Wv, Wg, Wo, p_Wh, p_Wl);

    // fused r,k,v,g GEMMs: gridDim.y = 4 slices * 128 row-tiles
    dim3 ggrid4(Cq / 128, 4 * (BT / 128));   // (8, 512)
    gemm_hmma<<<ggrid4, 256, GSMEM>>>(p_xh, p_xl, p_Wh, p_Wl, p_o4);

    float* p_r = p_o4 + (size_t)0 * BT * Cq;
    float* p_k = p_o4 + (size_t)1 * BT * Cq;
    float* p_v = p_o4 + (size_t)2 * BT * Cq;

    phaseA_kernel<<<NC * Bq * Hq, 256>>>(p_k, p_v, td);
    phaseB_kernel<<<Bq * Hq, 256>>>(td);
    phaseC_kernel<<<NC * Bq * Hq, 256, PC_SMEM>>>(p_r, p_k, p_v, td, tf, p_xo);

    gnorm_gate_kernel<<<(BT * Hq) / 8, 256>>>(lnw, lnb);

    // output GEMM: gridDim.y = 128 (g=0 => slice offsets applied via pointers)
    dim3 ggrid1(Cq / 128, BT / 128);         // (8, 128)
    gemm_hmma<<<ggrid1, 256, GSMEM>>>(p_yh, p_yl,
                                      p_Wh + (size_t)4 * Cq * Cq,
                                      p_Wl + (size_t)4 * Cq * Cq, out);
}